// round 4
// baseline (speedup 1.0000x reference)
#include <cuda_runtime.h>
#include <math.h>

#define B_    32
#define T_IN  1024
#define CIN   128
#define F_    256
#define TC    510
#define H_    512
#define G4    2048
#define M_    (TC*B_)
#define NCTA3 128

__device__ float g_wt[5*CIN*F_];
__device__ float g_y[(size_t)M_*F_];
__device__ float g_xp[(size_t)TC*G4*B_];
__device__ float g_h[2][B_*H_];
__device__ float g_udot[2][NCTA3][B_];
__device__ unsigned g_bar_cnt = 0;
__device__ unsigned g_bar_flag = 0;

__global__ void k0_wt(const float* __restrict__ cw) {
    int k = blockIdx.x, f = threadIdx.x;
    g_wt[(size_t)k*F_ + f] = cw[((size_t)f*CIN + (k & 127))*5 + (k >> 7)];
}

__global__ __launch_bounds__(256) void k1_conv(
    const float* __restrict__ x, const float* __restrict__ cb,
    const float* __restrict__ gamma, const float* __restrict__ beta,
    const float* __restrict__ mean, const float* __restrict__ var)
{
    __shared__ float As[16][132];
    __shared__ float Bs[16][132];
    const int n0 = blockIdx.x * 128, m0 = blockIdx.y * 128;
    const int tid = threadIdx.x, tx = tid & 15, ty = tid >> 4;
    float acc[8][8];
#pragma unroll
    for (int i = 0; i < 8; i++)
#pragma unroll
        for (int j = 0; j < 8; j++) acc[i][j] = 0.f;

    for (int ks = 0; ks < 40; ks++) {
        const int k0 = ks * 16;
#pragma unroll
        for (int i = 0; i < 2; i++) {
            int idx = tid + i*256, ml = idx >> 2, kc = (idx & 3)*4;
            int m = m0 + ml;
            float4 v = make_float4(0.f,0.f,0.f,0.f);
            if (m < M_) {
                int t = m >> 5, b = m & 31, k = k0 + kc;
                v = *(const float4*)(x + ((size_t)b*T_IN + (size_t)(2*t + (k>>7)))*CIN + (k&127));
            }
            As[kc][ml]=v.x; As[kc+1][ml]=v.y; As[kc+2][ml]=v.z; As[kc+3][ml]=v.w;
        }
#pragma unroll
        for (int i = 0; i < 2; i++) {
            int idx = tid + i*256, kr = idx >> 5, nc = (idx & 31)*4;
            float4 v = *(const float4*)(g_wt + (size_t)(k0+kr)*F_ + n0 + nc);
            Bs[kr][nc]=v.x; Bs[kr][nc+1]=v.y; Bs[kr][nc+2]=v.z; Bs[kr][nc+3]=v.w;
        }
        __syncthreads();
#pragma unroll
        for (int kk = 0; kk < 16; kk++) {
            float a[8], b[8];
            *(float4*)&a[0] = *(const float4*)&As[kk][ty*8];
            *(float4*)&a[4] = *(const float4*)&As[kk][ty*8+4];
            *(float4*)&b[0] = *(const float4*)&Bs[kk][tx*8];
            *(float4*)&b[4] = *(const float4*)&Bs[kk][tx*8+4];
#pragma unroll
            for (int i = 0; i < 8; i++)
#pragma unroll
                for (int j = 0; j < 8; j++) acc[i][j] = fmaf(a[i], b[j], acc[i][j]);
        }
        __syncthreads();
    }
    const int f0 = n0 + tx*8;
    float invs[8], adds[8], cbs[8];
#pragma unroll
    for (int j = 0; j < 8; j++) {
        float iv = gamma[f0+j] * rsqrtf(var[f0+j] + 1e-5f);
        invs[j] = iv; adds[j] = beta[f0+j] - mean[f0+j]*iv; cbs[j] = cb[f0+j];
    }
#pragma unroll
    for (int i = 0; i < 8; i++) {
        int m = m0 + ty*8 + i;
        if (m < M_) {
            float o[8];
#pragma unroll
            for (int j = 0; j < 8; j++)
                o[j] = fmaxf(acc[i][j] + cbs[j], 0.f)*invs[j] + adds[j];
            *(float4*)(g_y + (size_t)m*F_ + f0)   = make_float4(o[0],o[1],o[2],o[3]);
            *(float4*)(g_y + (size_t)m*F_ + f0+4) = make_float4(o[4],o[5],o[6],o[7]);
        }
    }
}

__global__ __launch_bounds__(256) void k2_xproj(
    const float* __restrict__ w_ih, const float* __restrict__ b_ih,
    const float* __restrict__ b_hh)
{
    extern __shared__ float sm2[];
    float* Ys = sm2;            // 32 x 257
    float* Ws = sm2 + 32*257;   // 32 x 128
    const int t = blockIdx.y, g0 = blockIdx.x * 128;
    const int tid = threadIdx.x, tx = tid & 15, ty = tid >> 4;

    const float* src = g_y + (size_t)t*32*F_;
#pragma unroll
    for (int q = 0; q < 8; q++) {
        int idx = tid + q*256, b = idx >> 6, f4 = idx & 63;
        float4 v = *(const float4*)(src + (size_t)b*F_ + f4*4);
        float* d = Ys + b*257 + f4*4;
        d[0]=v.x; d[1]=v.y; d[2]=v.z; d[3]=v.w;
    }
    float acc[8][2];
#pragma unroll
    for (int j = 0; j < 8; j++) { acc[j][0]=0.f; acc[j][1]=0.f; }

    for (int fs = 0; fs < 8; fs++) {
        __syncthreads();
#pragma unroll
        for (int q = 0; q < 4; q++) {
            int idx = tid + q*256, g = idx >> 3, f4 = idx & 7;
            float4 v = *(const float4*)(w_ih + (size_t)(g0+g)*F_ + fs*32 + f4*4);
            Ws[(f4*4  )*128+g]=v.x; Ws[(f4*4+1)*128+g]=v.y;
            Ws[(f4*4+2)*128+g]=v.z; Ws[(f4*4+3)*128+g]=v.w;
        }
        __syncthreads();
#pragma unroll
        for (int fr = 0; fr < 32; fr++) {
            float a[8];
            *(float4*)&a[0] = *(const float4*)(Ws + fr*128 + ty*8);
            *(float4*)&a[4] = *(const float4*)(Ws + fr*128 + ty*8 + 4);
            float y0 = Ys[(tx*2  )*257 + fs*32 + fr];
            float y1 = Ys[(tx*2+1)*257 + fs*32 + fr];
#pragma unroll
            for (int j = 0; j < 8; j++) {
                acc[j][0] = fmaf(a[j], y0, acc[j][0]);
                acc[j][1] = fmaf(a[j], y1, acc[j][1]);
            }
        }
    }
#pragma unroll
    for (int j = 0; j < 8; j++) {
        int g = g0 + ty*8 + j;
        float bias = b_ih[g] + b_hh[g];
        size_t base = ((size_t)t*G4 + g)*B_ + tx*2;
        g_xp[base] = acc[j][0] + bias;
        g_xp[base+1] = acc[j][1] + bias;
    }
}

__device__ __forceinline__ void grid_bar(unsigned sense) {
    __threadfence();
    __syncthreads();
    if (threadIdx.x == 0) {
        if (atomicAdd(&g_bar_cnt, 1u) == NCTA3 - 1u) {
            g_bar_cnt = 0u;
            __threadfence();
            *(volatile unsigned*)&g_bar_flag = sense;
        } else {
            while (*(volatile unsigned*)&g_bar_flag != sense) __nanosleep(64);
        }
        __threadfence();
    }
    __syncthreads();
}

__device__ __forceinline__ float sigf(float v) { return 1.f/(1.f + __expf(-v)); }

__global__ void __launch_bounds__(512, 1) k3_lstm(
    const float* __restrict__ w_hh, const float* __restrict__ w_uh,
    const float* __restrict__ b_uh, float* __restrict__ dout)
{
    extern __shared__ float dsm[];
    float* whh_s = dsm;           // 16 x 512
    float* hs    = dsm + 16*512;  // 32 x 512
    __shared__ float gm[16][33];
    __shared__ float u_s[32], ubin_s[32];
    __shared__ float red[16][32];
    __shared__ float cpart[4][32];
    __shared__ float wuh_s[4];

    const int cta = blockIdx.x, tid = threadIdx.x;
    const int lane = tid & 31, wid = tid >> 5;
#pragma unroll
    for (int q = 0; q < 4; q++) {
        int i4 = tid + q*512, r = i4 >> 7, kk = (i4 & 127)*4;
        int grow = (r >> 2)*512 + cta*4 + (r & 3);
        *(float4*)(whh_s + r*512 + kk) = *(const float4*)(w_hh + (size_t)grow*H_ + kk);
    }
    if (tid < 4) wuh_s[tid] = w_uh[cta*4 + tid];
    const float buh = b_uh[0];

    const int ggrp = wid >> 3, bq = wid & 7;
    const int r_l = ggrp*8 + (lane >> 2), b_l = bq*4 + (lane & 3);
    const int gidx_l = (r_l >> 2)*512 + cta*4 + (r_l & 3);

    float c_reg = 0.f;
    unsigned sense = 1u;
    __syncthreads();

    for (int t = 0; t < TC; ++t) {
        const int pp = t & 1, pq = pp ^ 1;
        if (t > 0) {
            {
                int b = tid & 31, ch = tid >> 5;
                const float* s8 = &g_udot[pq][ch*8][0];
                float s = 0.f;
#pragma unroll
                for (int c = 0; c < 8; c++) s += __ldcg(s8 + c*32 + b);
                red[ch][b] = s;
            }
            __syncthreads();
            if (tid < 32) {
                float tot = 0.f;
#pragma unroll
                for (int ch = 0; ch < 16; ch++) tot += red[ch][tid];
                float du = sigf(tot + buh);
                float up = u_s[tid], ub = ubin_s[tid];
                float un = ub*du + (1.f-ub)*(up + fminf(du, 1.f - up));
                u_s[tid] = un; ubin_s[tid] = rintf(un);
            }
        } else if (tid < 32) { u_s[tid] = 1.f; ubin_s[tid] = 1.f; }

        if (t == 0) {
            float4 z = make_float4(0.f,0.f,0.f,0.f);
#pragma unroll
            for (int q = 0; q < 8; q++) *(float4*)(hs + (tid + q*512)*4) = z;
        } else {
            const float4* s4 = (const float4*)g_h[pq];
#pragma unroll
            for (int q = 0; q < 8; q++)
                *(float4*)(hs + (tid + q*512)*4) = __ldcg(s4 + tid + q*512);
        }
        float xv = __ldcg(g_xp + ((size_t)t*G4 + gidx_l)*B_ + b_l);
        __syncthreads();

        float v[32];
#pragma unroll
        for (int j = 0; j < 32; j++) v[j] = 0.f;
#pragma unroll
        for (int i = 0; i < 4; i++) {
            int kk = 4*lane + 128*i;
            float4 h4[4];
#pragma unroll
            for (int bl = 0; bl < 4; bl++)
                h4[bl] = *(const float4*)(hs + (bq*4 + bl)*512 + kk);
#pragma unroll
            for (int gl = 0; gl < 8; gl++) {
                float4 w4 = *(const float4*)(whh_s + (ggrp*8 + gl)*512 + kk);
#pragma unroll
                for (int bl = 0; bl < 4; bl++) {
                    float s_ = v[gl*4 + bl];
                    s_ = fmaf(w4.x, h4[bl].x, s_);
                    s_ = fmaf(w4.y, h4[bl].y, s_);
                    s_ = fmaf(w4.z, h4[bl].z, s_);
                    s_ = fmaf(w4.w, h4[bl].w, s_);
                    v[gl*4 + bl] = s_;
                }
            }
        }
#pragma unroll
        for (int s = 16; s > 0; s >>= 1) {
#pragma unroll
            for (int j = 0; j < 16; j++) {
                if (j < s) {
                    bool up_ = (lane & s) != 0;
                    float keep = up_ ? v[j + s] : v[j];
                    float send = up_ ? v[j]     : v[j + s];
                    float rec = __shfl_xor_sync(0xffffffffu, send, s);
                    v[j] = keep + rec;
                }
            }
        }
        gm[r_l][b_l] = v[0] + xv;
        __syncthreads();

        if (tid < 128) {
            int jj = wid, b = lane;
            float ig = gm[jj][b], fg = gm[4+jj][b], gg = gm[8+jj][b], og = gm[12+jj][b];
            float c = c_reg;
            float ct = sigf(fg)*c + sigf(ig)*tanhf(gg);
            float ht = sigf(og)*tanhf(ct);
            float ub = ubin_s[b];
            float hp = hs[b*512 + cta*4 + jj];
            float cn = ub*ct + (1.f-ub)*c;
            float hn = ub*ht + (1.f-ub)*hp;
            c_reg = cn;
            g_h[pp][b*512 + cta*4 + jj] = hn;
            if (t == TC-1) dout[(size_t)b*H_ + cta*4 + jj] = hn;
            cpart[jj][b] = cn * wuh_s[jj];
        }
        __syncthreads();
        if (tid < 32)
            g_udot[pp][cta][tid] = cpart[0][tid]+cpart[1][tid]+cpart[2][tid]+cpart[3][tid];

        grid_bar(sense);
        sense ^= 1u;
    }
}

extern "C" void kernel_launch(void* const* d_in, const int* in_sizes, int n_in,
                              void* d_out, int out_size) {
    const float* x     = (const float*)d_in[0];
    const float* cw    = (const float*)d_in[1];
    const float* cb    = (const float*)d_in[2];
    const float* gamma = (const float*)d_in[3];
    const float* beta  = (const float*)d_in[4];
    const float* mean  = (const float*)d_in[5];
    const float* var   = (const float*)d_in[6];
    const float* w_ih  = (const float*)d_in[7];
    const float* w_hh  = (const float*)d_in[8];
    const float* b_ih  = (const float*)d_in[9];
    const float* b_hh  = (const float*)d_in[10];
    const float* w_uh  = (const float*)d_in[11];
    const float* b_uh  = (const float*)d_in[12];
    float* dout = (float*)d_out;

    cudaFuncSetAttribute(k2_xproj, cudaFuncAttributeMaxDynamicSharedMemorySize, 49280);
    cudaFuncSetAttribute(k3_lstm,  cudaFuncAttributeMaxDynamicSharedMemorySize, 98304);

    k0_wt<<<640, 256>>>(cw);
    k1_conv<<<dim3(2, 128), 256>>>(x, cb, gamma, beta, mean, var);
    k2_xproj<<<dim3(16, TC), 256, 49280>>>(w_ih, b_ih, b_hh);
    k3_lstm<<<NCTA3, 512, 98304>>>(w_hh, w_uh, b_uh, dout);
}